// round 1
// baseline (speedup 1.0000x reference)
#include <cuda_runtime.h>
#include <math.h>

#define BB  2
#define SS  2048
#define DD  1024
#define HH  16
#define DKK 64

// Scratch (allocation-free rule: __device__ globals)
__device__ float g_qp[BB*HH*SS*DKK];   // [B,H,S,DK]
__device__ float g_kp[BB*HH*SS*DKK];
__device__ float g_vp[BB*HH*SS*DKK];
__device__ float g_ao[BB*SS*HH*DKK];   // [B,S,H*DK] concat layout

// ---------------------------------------------------------------------------
// Projection GEMM: P[b,h,s,k] = sum_d X[b,s,d] * W[h,d,k]
// Block tile: 128 rows (s) x 64 cols (full DK of one head). BK=16.
// 256 threads, each computes 8x4.
// ---------------------------------------------------------------------------
__global__ __launch_bounds__(256) void proj_kernel(const float* __restrict__ X,
                                                   const float* __restrict__ W,
                                                   int which) {
    float* P = (which == 0) ? g_qp : (which == 1) ? g_kp : g_vp;
    const int tile = blockIdx.x, h = blockIdx.y, b = blockIdx.z;
    const int tid = threadIdx.x;
    const int tx = tid & 15;        // col group (x4)
    const int ty = tid >> 4;        // row group (x8)

    __shared__ float As[128][17];
    __shared__ float Bs[16][64];

    const float* Xb = X + (size_t)(b * SS + tile * 128) * DD;
    const float* Wh = W + (size_t)h * DD * DKK;

    float acc[8][4];
#pragma unroll
    for (int r = 0; r < 8; r++)
#pragma unroll
        for (int c = 0; c < 4; c++) acc[r][c] = 0.f;

    const int arow = tid >> 1;          // 0..127
    const int acol = (tid & 1) * 8;     // 0 or 8
    const int brow = tid >> 4;          // 0..15
    const int bcol = (tid & 15) * 4;    // 0..60

    for (int d0 = 0; d0 < DD; d0 += 16) {
        float4 a0 = *(const float4*)(Xb + (size_t)arow * DD + d0 + acol);
        float4 a1 = *(const float4*)(Xb + (size_t)arow * DD + d0 + acol + 4);
        As[arow][acol + 0] = a0.x; As[arow][acol + 1] = a0.y;
        As[arow][acol + 2] = a0.z; As[arow][acol + 3] = a0.w;
        As[arow][acol + 4] = a1.x; As[arow][acol + 5] = a1.y;
        As[arow][acol + 6] = a1.z; As[arow][acol + 7] = a1.w;
        *(float4*)&Bs[brow][bcol] =
            *(const float4*)(Wh + (size_t)(d0 + brow) * DKK + bcol);
        __syncthreads();

#pragma unroll
        for (int kk = 0; kk < 16; kk++) {
            float4 bv = *(const float4*)&Bs[kk][tx * 4];
#pragma unroll
            for (int r = 0; r < 8; r++) {
                float a = As[ty * 8 + r][kk];
                acc[r][0] = fmaf(a, bv.x, acc[r][0]);
                acc[r][1] = fmaf(a, bv.y, acc[r][1]);
                acc[r][2] = fmaf(a, bv.z, acc[r][2]);
                acc[r][3] = fmaf(a, bv.w, acc[r][3]);
            }
        }
        __syncthreads();
    }

    float* Pb = P + ((size_t)(b * HH + h) * SS + tile * 128) * DKK;
#pragma unroll
    for (int r = 0; r < 8; r++) {
        float4 v = make_float4(acc[r][0], acc[r][1], acc[r][2], acc[r][3]);
        *(float4*)(Pb + (size_t)(ty * 8 + r) * DKK + tx * 4) = v;
    }
}

// ---------------------------------------------------------------------------
// Causal flash attention, fp32. One thread = one query row. Block = 128 rows.
// K/V tiles of 32x64 staged in smem; all compute reads are warp-broadcast.
// ---------------------------------------------------------------------------
__global__ __launch_bounds__(128) void attn_kernel() {
    const int tile = blockIdx.x;   // S/128
    const int h = blockIdx.y, b = blockIdx.z;
    const int tid = threadIdx.x;
    const int qi = tile * 128 + tid;

    const float* qp = g_qp + (size_t)(b * HH + h) * SS * DKK;
    const float* kp = g_kp + (size_t)(b * HH + h) * SS * DKK;
    const float* vp = g_vp + (size_t)(b * HH + h) * SS * DKK;

    __shared__ float Ks[32 * 64];
    __shared__ float Vs[32 * 64];

    float q[64], o[64];
    const float scale = 0.125f;  // 1/sqrt(64)
#pragma unroll
    for (int d = 0; d < 64; d += 4) {
        float4 v = *(const float4*)(qp + (size_t)qi * 64 + d);
        q[d + 0] = v.x * scale; q[d + 1] = v.y * scale;
        q[d + 2] = v.z * scale; q[d + 3] = v.w * scale;
    }
#pragma unroll
    for (int d = 0; d < 64; d++) o[d] = 0.f;

    float m = -INFINITY, l = 0.f;
    const int ntiles = tile * 4 + 4;   // causal: keys up to block's last row

    for (int kt = 0; kt < ntiles; kt++) {
        const float4* ksrc = (const float4*)(kp + (size_t)kt * 32 * 64);
        const float4* vsrc = (const float4*)(vp + (size_t)kt * 32 * 64);
#pragma unroll
        for (int u = 0; u < 4; u++) {
            int f = tid + u * 128;   // 512 float4s per tile
            ((float4*)Ks)[f] = ksrc[f];
            ((float4*)Vs)[f] = vsrc[f];
        }
        __syncthreads();

        float s[32];
        float tmax = -INFINITY;
        const int kbase = kt * 32;
#pragma unroll
        for (int j = 0; j < 32; j++) {
            float a0 = 0.f, a1 = 0.f, a2 = 0.f, a3 = 0.f;
            const float* kr = &Ks[j * 64];
#pragma unroll
            for (int d = 0; d < 64; d += 4) {
                a0 = fmaf(q[d + 0], kr[d + 0], a0);
                a1 = fmaf(q[d + 1], kr[d + 1], a1);
                a2 = fmaf(q[d + 2], kr[d + 2], a2);
                a3 = fmaf(q[d + 3], kr[d + 3], a3);
            }
            float sc = (a0 + a1) + (a2 + a3);
            s[j] = (kbase + j <= qi) ? sc : -INFINITY;
            tmax = fmaxf(tmax, s[j]);
        }

        float mn = fmaxf(m, tmax);          // finite from first tile on
        float corr = __expf(m - mn);        // exp(-inf)=0 on first tile
        l *= corr;
#pragma unroll
        for (int d = 0; d < 64; d++) o[d] *= corr;

#pragma unroll
        for (int j = 0; j < 32; j++) {
            float p = __expf(s[j] - mn);    // masked: exp(-inf)=0
            l += p;
            const float* vr = &Vs[j * 64];
#pragma unroll
            for (int d = 0; d < 64; d++) o[d] = fmaf(p, vr[d], o[d]);
        }
        m = mn;
        __syncthreads();
    }

    const float inv = 1.f / l;
    float* ao = g_ao + ((size_t)(b * SS + qi) * (HH * DKK)) + h * DKK;
#pragma unroll
    for (int d = 0; d < 64; d += 4) {
        float4 v = make_float4(o[d] * inv, o[d + 1] * inv,
                               o[d + 2] * inv, o[d + 3] * inv);
        *(float4*)(ao + d) = v;
    }
}

// ---------------------------------------------------------------------------
// Output projection: Y[m,n] = sum_k X[m,k] * Wo[n,k] + bo[n]
// X = g_ao [B*S, 1024], Wo [1024, 1024] (row n, k contiguous). 128x64 tile.
// ---------------------------------------------------------------------------
__global__ __launch_bounds__(256) void outproj_kernel(const float* __restrict__ Wo,
                                                      const float* __restrict__ bo,
                                                      float* __restrict__ Y) {
    const int mt = blockIdx.x, nt = blockIdx.y;
    const int tid = threadIdx.x;
    const int tx = tid & 15;
    const int ty = tid >> 4;

    __shared__ float As[128][17];
    __shared__ float Bs[16][68];   // row stride 68 floats = 272B (16B aligned)

    const float* Xb = g_ao + (size_t)mt * 128 * DD;

    float acc[8][4];
#pragma unroll
    for (int r = 0; r < 8; r++)
#pragma unroll
        for (int c = 0; c < 4; c++) acc[r][c] = 0.f;

    const int arow = tid >> 1;
    const int acol = (tid & 1) * 8;
    const int bn  = tid >> 2;         // 0..63  (n within tile)
    const int bk0 = (tid & 3) * 4;    // 0,4,8,12

    for (int k0 = 0; k0 < DD; k0 += 16) {
        float4 a0 = *(const float4*)(Xb + (size_t)arow * DD + k0 + acol);
        float4 a1 = *(const float4*)(Xb + (size_t)arow * DD + k0 + acol + 4);
        As[arow][acol + 0] = a0.x; As[arow][acol + 1] = a0.y;
        As[arow][acol + 2] = a0.z; As[arow][acol + 3] = a0.w;
        As[arow][acol + 4] = a1.x; As[arow][acol + 5] = a1.y;
        As[arow][acol + 6] = a1.z; As[arow][acol + 7] = a1.w;
        float4 w = *(const float4*)(Wo + (size_t)(nt * 64 + bn) * DD + k0 + bk0);
        Bs[bk0 + 0][bn] = w.x; Bs[bk0 + 1][bn] = w.y;
        Bs[bk0 + 2][bn] = w.z; Bs[bk0 + 3][bn] = w.w;
        __syncthreads();

#pragma unroll
        for (int kk = 0; kk < 16; kk++) {
            float4 bv = *(const float4*)&Bs[kk][tx * 4];
#pragma unroll
            for (int r = 0; r < 8; r++) {
                float a = As[ty * 8 + r][kk];
                acc[r][0] = fmaf(a, bv.x, acc[r][0]);
                acc[r][1] = fmaf(a, bv.y, acc[r][1]);
                acc[r][2] = fmaf(a, bv.z, acc[r][2]);
                acc[r][3] = fmaf(a, bv.w, acc[r][3]);
            }
        }
        __syncthreads();
    }

    float4 bias = *(const float4*)(bo + nt * 64 + tx * 4);
#pragma unroll
    for (int r = 0; r < 8; r++) {
        float4 v = make_float4(acc[r][0] + bias.x, acc[r][1] + bias.y,
                               acc[r][2] + bias.z, acc[r][3] + bias.w);
        *(float4*)(Y + (size_t)(mt * 128 + ty * 8 + r) * DD + nt * 64 + tx * 4) = v;
    }
}

// ---------------------------------------------------------------------------
extern "C" void kernel_launch(void* const* d_in, const int* in_sizes, int n_in,
                              void* d_out, int out_size) {
    const float* query = (const float*)d_in[0];
    const float* key   = (const float*)d_in[1];
    const float* value = (const float*)d_in[2];
    const float* Wq    = (const float*)d_in[3];
    const float* Wk    = (const float*)d_in[4];
    const float* Wv    = (const float*)d_in[5];
    const float* Wo    = (const float*)d_in[6];
    const float* bo    = (const float*)d_in[7];
    float* out = (float*)d_out;

    dim3 pg(SS / 128, HH, BB);
    proj_kernel<<<pg, 256>>>(query, Wq, 0);
    proj_kernel<<<pg, 256>>>(key,   Wk, 1);
    proj_kernel<<<pg, 256>>>(value, Wv, 2);

    attn_kernel<<<dim3(SS / 128, HH, BB), 128>>>();

    outproj_kernel<<<dim3(BB * SS / 128, DD / 64), 256>>>(Wo, bo, out);
}

// round 3
// speedup vs baseline: 2.7984x; 2.7984x over previous
#include <cuda_runtime.h>
#include <cuda_fp16.h>
#include <math.h>
#include <stdint.h>

#define BB  2
#define SS  2048
#define DD  1024
#define HH  16
#define DKK 64

// Scratch (allocation-free rule: __device__ globals)
__device__ float  g_qp[BB*HH*SS*DKK];   // [B,H,S,DK] fp32
__device__ float  g_kp[BB*HH*SS*DKK];
__device__ __half g_vp[BB*HH*SS*DKK];   // fp16
__device__ float  g_ao[BB*SS*HH*DKK];   // [B,S,H*DK] fp32

// ---------------------------------------------------------------------------
// helpers
// ---------------------------------------------------------------------------
__device__ __forceinline__ float tf32r(float x) {
    uint32_t u;
    asm("cvt.rna.tf32.f32 %0, %1;" : "=r"(u) : "f"(x));
    return __uint_as_float(u);
}
__device__ __forceinline__ float4 tf32r4(float4 v) {
    return make_float4(tf32r(v.x), tf32r(v.y), tf32r(v.z), tf32r(v.w));
}
__device__ __forceinline__ void mma_tf32(float* d, const uint32_t* a, const uint32_t* b) {
    asm volatile(
        "mma.sync.aligned.m16n8k8.row.col.f32.tf32.tf32.f32 "
        "{%0,%1,%2,%3}, {%4,%5,%6,%7}, {%8,%9}, {%0,%1,%2,%3};"
        : "+f"(d[0]), "+f"(d[1]), "+f"(d[2]), "+f"(d[3])
        : "r"(a[0]), "r"(a[1]), "r"(a[2]), "r"(a[3]), "r"(b[0]), "r"(b[1]));
}
__device__ __forceinline__ void mma_f16(float* d, const uint32_t* a, const uint32_t* b) {
    asm volatile(
        "mma.sync.aligned.m16n8k16.row.col.f32.f16.f16.f32 "
        "{%0,%1,%2,%3}, {%4,%5,%6,%7}, {%8,%9}, {%0,%1,%2,%3};"
        : "+f"(d[0]), "+f"(d[1]), "+f"(d[2]), "+f"(d[3])
        : "r"(a[0]), "r"(a[1]), "r"(a[2]), "r"(a[3]), "r"(b[0]), "r"(b[1]));
}

// ---------------------------------------------------------------------------
// tf32 projection GEMM: P[b,h,s,k] = sum_d X[b,s,d] * W[h,d,k]
// Block 128(M)x64(N), BK=32, 256 thr = 8 warps (4m x 2n), warp tile 32x32.
// which: 0->g_qp(f32), 1->g_kp(f32), 2->g_vp(f16)
// ---------------------------------------------------------------------------
__global__ __launch_bounds__(256) void proj_tf32(const float* __restrict__ X,
                                                 const float* __restrict__ W,
                                                 int which) {
    const int tile = blockIdx.x, h = blockIdx.y, b = blockIdx.z;
    const int tid = threadIdx.x;
    const int warp = tid >> 5, lane = tid & 31;
    const int wm = warp & 3, wn = warp >> 2;
    const int lq = lane >> 2, lp = lane & 3;

    __shared__ float As[128][36];   // stride 36: lq*4+lp bank map
    __shared__ float Bs[32][72];    // stride 72: lp*8+lq bank map

    const float* Xb = X + (size_t)(b * SS + tile * 128) * DD;
    const float* Wh = W + (size_t)h * DD * DKK;

    float acc[2][4][4];
#pragma unroll
    for (int mi = 0; mi < 2; mi++)
#pragma unroll
        for (int ni = 0; ni < 4; ni++)
#pragma unroll
            for (int c = 0; c < 4; c++) acc[mi][ni][c] = 0.f;

    const int ar = tid >> 1, ac = (tid & 1) * 16;
    const int br = tid >> 3, bc = (tid & 7) * 8;

    for (int k0 = 0; k0 < DD; k0 += 32) {
        const float* asrc = Xb + (size_t)ar * DD + k0 + ac;
#pragma unroll
        for (int i = 0; i < 4; i++)
            *(float4*)&As[ar][ac + i * 4] = tf32r4(*(const float4*)(asrc + i * 4));
        const float* bsrc = Wh + (size_t)(k0 + br) * DKK + bc;
        *(float4*)&Bs[br][bc]     = tf32r4(*(const float4*)(bsrc));
        *(float4*)&Bs[br][bc + 4] = tf32r4(*(const float4*)(bsrc + 4));
        __syncthreads();

#pragma unroll
        for (int kk = 0; kk < 4; kk++) {
            uint32_t af[2][4];
#pragma unroll
            for (int mi = 0; mi < 2; mi++) {
                const int m0 = wm * 32 + mi * 16;
                af[mi][0] = *(const uint32_t*)&As[m0 + lq][kk * 8 + lp];
                af[mi][1] = *(const uint32_t*)&As[m0 + lq + 8][kk * 8 + lp];
                af[mi][2] = *(const uint32_t*)&As[m0 + lq][kk * 8 + lp + 4];
                af[mi][3] = *(const uint32_t*)&As[m0 + lq + 8][kk * 8 + lp + 4];
            }
            uint32_t bf[4][2];
#pragma unroll
            for (int ni = 0; ni < 4; ni++) {
                const int n = wn * 32 + ni * 8 + lq;
                bf[ni][0] = *(const uint32_t*)&Bs[kk * 8 + lp][n];
                bf[ni][1] = *(const uint32_t*)&Bs[kk * 8 + lp + 4][n];
            }
#pragma unroll
            for (int mi = 0; mi < 2; mi++)
#pragma unroll
                for (int ni = 0; ni < 4; ni++)
                    mma_tf32(acc[mi][ni], af[mi], bf[ni]);
        }
        __syncthreads();
    }

    const int srow = tile * 128 + wm * 32;
    const size_t base = (size_t)(b * HH + h) * SS * DKK;
    if (which < 2) {
        float* P = which ? g_kp : g_qp;
#pragma unroll
        for (int mi = 0; mi < 2; mi++)
#pragma unroll
            for (int ni = 0; ni < 4; ni++) {
                const int r0 = srow + mi * 16 + lq;
                const int col = wn * 32 + ni * 8 + 2 * lp;
                *(float2*)(P + base + (size_t)r0 * DKK + col) =
                    make_float2(acc[mi][ni][0], acc[mi][ni][1]);
                *(float2*)(P + base + (size_t)(r0 + 8) * DKK + col) =
                    make_float2(acc[mi][ni][2], acc[mi][ni][3]);
            }
    } else {
        __half* V = g_vp;
#pragma unroll
        for (int mi = 0; mi < 2; mi++)
#pragma unroll
            for (int ni = 0; ni < 4; ni++) {
                const int r0 = srow + mi * 16 + lq;
                const int col = wn * 32 + ni * 8 + 2 * lp;
                union { uint32_t u; __half2 h; } p0, p1;
                p0.h = __floats2half2_rn(acc[mi][ni][0], acc[mi][ni][1]);
                p1.h = __floats2half2_rn(acc[mi][ni][2], acc[mi][ni][3]);
                *(uint32_t*)(V + base + (size_t)r0 * DKK + col) = p0.u;
                *(uint32_t*)(V + base + (size_t)(r0 + 8) * DKK + col) = p1.u;
            }
    }
}

// ---------------------------------------------------------------------------
// Flash attention: QK^T tf32 mma, softmax fp32, PV fp16 mma.
// Block: 64 q-rows, 4 warps (m16 each). KV tile = 64.
// ---------------------------------------------------------------------------
__global__ __launch_bounds__(128) void attn_kernel() {
    const int qtile = blockIdx.x;      // S/64
    const int h = blockIdx.y, b = blockIdx.z;
    const int tid = threadIdx.x;
    const int wid = tid >> 5;
    const int lane = tid & 31;
    const int lq = lane >> 2;
    const int lp = lane & 3;

    const float*  qp = g_qp + (size_t)(b * HH + h) * SS * DKK;
    const float*  kp = g_kp + (size_t)(b * HH + h) * SS * DKK;
    const __half* vp = g_vp + (size_t)(b * HH + h) * SS * DKK;

    __shared__ float  Ks[64][68];    // tf32 bits; stride 68 -> lq*4+lp banks
    __shared__ __half VsT[64][72];   // VsT[dk][key]; stride 72h=36w -> lq*4+lp

    // --- Q fragments: 8 k-steps (k8), pre-scaled, tf32 ---
    const int qrow0 = qtile * 64 + wid * 16;
    uint32_t aq[8][4];
#pragma unroll
    for (int kk = 0; kk < 8; kk++) {
        const int d0 = kk * 8 + lp;
        aq[kk][0] = __float_as_uint(tf32r(0.125f * qp[(size_t)(qrow0 + lq)     * DKK + d0]));
        aq[kk][1] = __float_as_uint(tf32r(0.125f * qp[(size_t)(qrow0 + lq + 8) * DKK + d0]));
        aq[kk][2] = __float_as_uint(tf32r(0.125f * qp[(size_t)(qrow0 + lq)     * DKK + d0 + 4]));
        aq[kk][3] = __float_as_uint(tf32r(0.125f * qp[(size_t)(qrow0 + lq + 8) * DKK + d0 + 4]));
    }

    float oacc[8][4];
#pragma unroll
    for (int j = 0; j < 8; j++)
#pragma unroll
        for (int c = 0; c < 4; c++) oacc[j][c] = 0.f;

    float m0 = -INFINITY, m1 = -INFINITY;
    float l0 = 0.f, l1 = 0.f;

    const int ntiles = qtile + 1;
    const int qi0 = qrow0 + lq;
    const int qi1 = qi0 + 8;

    for (int kt = 0; kt < ntiles; kt++) {
        // ---- stage K tile (fp32 -> tf32) ----
        {
            const int row = tid >> 1;
            const int cb = (tid & 1) * 32;
            const float* src = kp + (size_t)(kt * 64 + row) * DKK + cb;
#pragma unroll
            for (int i = 0; i < 8; i++)
                *(float4*)&Ks[row][cb + i * 4] = tf32r4(*(const float4*)(src + i * 4));
        }
        // ---- stage V tile transposed (fp16) ----
        {
            const int key = tid & 63;
            const int dkb = (tid >> 6) * 32;
            const __half* src = vp + (size_t)(kt * 64 + key) * DKK + dkb;
            union { uint4 u4[4]; __half hh[32]; } buf;
#pragma unroll
            for (int i = 0; i < 4; i++) buf.u4[i] = *(const uint4*)(src + i * 8);
#pragma unroll
            for (int j = 0; j < 32; j++) VsT[dkb + j][key] = buf.hh[j];
        }
        __syncthreads();

        // ---- S = Q @ K^T (tf32) ----
        float sacc[8][4];
#pragma unroll
        for (int j = 0; j < 8; j++)
#pragma unroll
            for (int c = 0; c < 4; c++) sacc[j][c] = 0.f;

#pragma unroll
        for (int kk = 0; kk < 8; kk++) {
#pragma unroll
            for (int j = 0; j < 8; j++) {
                uint32_t bk[2];
                bk[0] = *(const uint32_t*)&Ks[j * 8 + lq][kk * 8 + lp];
                bk[1] = *(const uint32_t*)&Ks[j * 8 + lq][kk * 8 + lp + 4];
                mma_tf32(sacc[j], aq[kk], bk);
            }
        }

        // ---- causal mask (diagonal tile only) ----
        if (kt == qtile) {
#pragma unroll
            for (int j = 0; j < 8; j++) {
                const int kj = kt * 64 + j * 8 + lp * 2;
                if (kj     > qi0) sacc[j][0] = -INFINITY;
                if (kj + 1 > qi0) sacc[j][1] = -INFINITY;
                if (kj     > qi1) sacc[j][2] = -INFINITY;
                if (kj + 1 > qi1) sacc[j][3] = -INFINITY;
            }
        }

        // ---- online softmax ----
        float t0 = -INFINITY, t1 = -INFINITY;
#pragma unroll
        for (int j = 0; j < 8; j++) {
            t0 = fmaxf(t0, fmaxf(sacc[j][0], sacc[j][1]));
            t1 = fmaxf(t1, fmaxf(sacc[j][2], sacc[j][3]));
        }
        t0 = fmaxf(t0, __shfl_xor_sync(0xffffffff, t0, 1));
        t0 = fmaxf(t0, __shfl_xor_sync(0xffffffff, t0, 2));
        t1 = fmaxf(t1, __shfl_xor_sync(0xffffffff, t1, 1));
        t1 = fmaxf(t1, __shfl_xor_sync(0xffffffff, t1, 2));

        const float mn0 = fmaxf(m0, t0), mn1 = fmaxf(m1, t1);
        const float corr0 = __expf(m0 - mn0), corr1 = __expf(m1 - mn1);
        m0 = mn0; m1 = mn1;

        float ls0 = 0.f, ls1 = 0.f;
#pragma unroll
        for (int j = 0; j < 8; j++) {
            sacc[j][0] = __expf(sacc[j][0] - mn0);
            sacc[j][1] = __expf(sacc[j][1] - mn0);
            sacc[j][2] = __expf(sacc[j][2] - mn1);
            sacc[j][3] = __expf(sacc[j][3] - mn1);
            ls0 += sacc[j][0] + sacc[j][1];
            ls1 += sacc[j][2] + sacc[j][3];
        }
        l0 = l0 * corr0 + ls0;
        l1 = l1 * corr1 + ls1;
#pragma unroll
        for (int j = 0; j < 8; j++) {
            oacc[j][0] *= corr0; oacc[j][1] *= corr0;
            oacc[j][2] *= corr1; oacc[j][3] *= corr1;
        }

        // ---- P (fp16, register identity) @ V ----
#pragma unroll
        for (int ks = 0; ks < 4; ks++) {
            uint32_t ap[4];
            union { uint32_t u; __half2 h; } c0, c1, c2, c3;
            c0.h = __floats2half2_rn(sacc[2*ks][0],   sacc[2*ks][1]);
            c1.h = __floats2half2_rn(sacc[2*ks][2],   sacc[2*ks][3]);
            c2.h = __floats2half2_rn(sacc[2*ks+1][0], sacc[2*ks+1][1]);
            c3.h = __floats2half2_rn(sacc[2*ks+1][2], sacc[2*ks+1][3]);
            ap[0] = c0.u; ap[1] = c1.u; ap[2] = c2.u; ap[3] = c3.u;
#pragma unroll
            for (int j = 0; j < 8; j++) {
                uint32_t bv[2];
                bv[0] = *(const uint32_t*)&VsT[j * 8 + lq][ks * 16 + lp * 2];
                bv[1] = *(const uint32_t*)&VsT[j * 8 + lq][ks * 16 + lp * 2 + 8];
                mma_f16(oacc[j], ap, bv);
            }
        }
        __syncthreads();
    }

    l0 += __shfl_xor_sync(0xffffffff, l0, 1);
    l0 += __shfl_xor_sync(0xffffffff, l0, 2);
    l1 += __shfl_xor_sync(0xffffffff, l1, 1);
    l1 += __shfl_xor_sync(0xffffffff, l1, 2);
    const float inv0 = 1.f / l0, inv1 = 1.f / l1;

    float* ao = g_ao + (size_t)b * SS * DD + (size_t)h * DKK;
#pragma unroll
    for (int j = 0; j < 8; j++) {
        const int dk = j * 8 + lp * 2;
        *(float2*)(ao + (size_t)qi0 * DD + dk) =
            make_float2(oacc[j][0] * inv0, oacc[j][1] * inv0);
        *(float2*)(ao + (size_t)qi1 * DD + dk) =
            make_float2(oacc[j][2] * inv1, oacc[j][3] * inv1);
    }
}

// ---------------------------------------------------------------------------
// tf32 output projection: Y[m,n] = sum_k X[m,k] * Wo[n,k] + bo[n]
// Same skeleton as proj_tf32; B tile transposed from Wo rows.
// ---------------------------------------------------------------------------
__global__ __launch_bounds__(256) void outproj_tf32(const float* __restrict__ Wo,
                                                    const float* __restrict__ bo,
                                                    float* __restrict__ Y) {
    const int mt = blockIdx.x, nt = blockIdx.y;
    const int tid = threadIdx.x;
    const int warp = tid >> 5, lane = tid & 31;
    const int wm = warp & 3, wn = warp >> 2;
    const int lq = lane >> 2, lp = lane & 3;

    __shared__ float As[128][36];
    __shared__ float Bs[32][72];

    const float* Xb = g_ao + (size_t)mt * 128 * DD;

    float acc[2][4][4];
#pragma unroll
    for (int mi = 0; mi < 2; mi++)
#pragma unroll
        for (int ni = 0; ni < 4; ni++)
#pragma unroll
            for (int c = 0; c < 4; c++) acc[mi][ni][c] = 0.f;

    const int ar = tid >> 1, ac = (tid & 1) * 16;
    const int bn = tid >> 2, bkc = (tid & 3) * 8;   // 64 n-rows, 4 k-chunks

    for (int k0 = 0; k0 < DD; k0 += 32) {
        const float* asrc = Xb + (size_t)ar * DD + k0 + ac;
#pragma unroll
        for (int i = 0; i < 4; i++)
            *(float4*)&As[ar][ac + i * 4] = tf32r4(*(const float4*)(asrc + i * 4));
        const float* wsrc = Wo + (size_t)(nt * 64 + bn) * DD + k0 + bkc;
        float4 w0 = tf32r4(*(const float4*)(wsrc));
        float4 w1 = tf32r4(*(const float4*)(wsrc + 4));
        Bs[bkc + 0][bn] = w0.x; Bs[bkc + 1][bn] = w0.y;
        Bs[bkc + 2][bn] = w0.z; Bs[bkc + 3][bn] = w0.w;
        Bs[bkc + 4][bn] = w1.x; Bs[bkc + 5][bn] = w1.y;
        Bs[bkc + 6][bn] = w1.z; Bs[bkc + 7][bn] = w1.w;
        __syncthreads();

#pragma unroll
        for (int kk = 0; kk < 4; kk++) {
            uint32_t af[2][4];
#pragma unroll
            for (int mi = 0; mi < 2; mi++) {
                const int m0 = wm * 32 + mi * 16;
                af[mi][0] = *(const uint32_t*)&As[m0 + lq][kk * 8 + lp];
                af[mi][1] = *(const uint32_t*)&As[m0 + lq + 8][kk * 8 + lp];
                af[mi][2] = *(const uint32_t*)&As[m0 + lq][kk * 8 + lp + 4];
                af[mi][3] = *(const uint32_t*)&As[m0 + lq + 8][kk * 8 + lp + 4];
            }
            uint32_t bf[4][2];
#pragma unroll
            for (int ni = 0; ni < 4; ni++) {
                const int n = wn * 32 + ni * 8 + lq;
                bf[ni][0] = *(const uint32_t*)&Bs[kk * 8 + lp][n];
                bf[ni][1] = *(const uint32_t*)&Bs[kk * 8 + lp + 4][n];
            }
#pragma unroll
            for (int mi = 0; mi < 2; mi++)
#pragma unroll
                for (int ni = 0; ni < 4; ni++)
                    mma_tf32(acc[mi][ni], af[mi], bf[ni]);
        }
        __syncthreads();
    }

#pragma unroll
    for (int mi = 0; mi < 2; mi++)
#pragma unroll
        for (int ni = 0; ni < 4; ni++) {
            const int r0 = mt * 128 + wm * 32 + mi * 16 + lq;
            const int col = nt * 64 + wn * 32 + ni * 8 + 2 * lp;
            const float b0 = bo[col], b1 = bo[col + 1];
            *(float2*)(Y + (size_t)r0 * DD + col) =
                make_float2(acc[mi][ni][0] + b0, acc[mi][ni][1] + b1);
            *(float2*)(Y + (size_t)(r0 + 8) * DD + col) =
                make_float2(acc[mi][ni][2] + b0, acc[mi][ni][3] + b1);
        }
}

// ---------------------------------------------------------------------------
extern "C" void kernel_launch(void* const* d_in, const int* in_sizes, int n_in,
                              void* d_out, int out_size) {
    const float* query = (const float*)d_in[0];
    const float* key   = (const float*)d_in[1];
    const float* value = (const float*)d_in[2];
    const float* Wq    = (const float*)d_in[3];
    const float* Wk    = (const float*)d_in[4];
    const float* Wv    = (const float*)d_in[5];
    const float* Wo    = (const float*)d_in[6];
    const float* bo    = (const float*)d_in[7];
    float* out = (float*)d_out;

    dim3 pg(SS / 128, HH, BB);
    proj_tf32<<<pg, 256>>>(query, Wq, 0);
    proj_tf32<<<pg, 256>>>(key,   Wk, 1);
    proj_tf32<<<pg, 256>>>(value, Wv, 2);

    attn_kernel<<<dim3(SS / 64, HH, BB), 128>>>();

    outproj_tf32<<<dim3(BB * SS / 128, DD / 64), 256>>>(Wo, bo, out);
}

// round 4
// speedup vs baseline: 4.7429x; 1.6949x over previous
#include <cuda_runtime.h>
#include <cuda_fp16.h>
#include <math.h>
#include <stdint.h>

#define BB  2
#define SS  2048
#define DD  1024
#define HH  16
#define DKK 64

// Scratch (allocation-free rule: __device__ globals), all fp16
__device__ __half g_qp[BB*HH*SS*DKK];   // [B,H,S,DK], pre-scaled by 1/8
__device__ __half g_kp[BB*HH*SS*DKK];
__device__ __half g_vp[BB*HH*SS*DKK];
__device__ __half g_ao[BB*SS*HH*DKK];   // [B,S,H*DK]

// ---------------------------------------------------------------------------
// helpers
// ---------------------------------------------------------------------------
__device__ __forceinline__ void ldsm4(uint32_t* r, const void* p) {
    uint32_t a = (uint32_t)__cvta_generic_to_shared(p);
    asm volatile("ldmatrix.sync.aligned.m8n8.x4.shared.b16 {%0,%1,%2,%3}, [%4];"
        : "=r"(r[0]), "=r"(r[1]), "=r"(r[2]), "=r"(r[3]) : "r"(a));
}
__device__ __forceinline__ void ldsm4t(uint32_t* r, const void* p) {
    uint32_t a = (uint32_t)__cvta_generic_to_shared(p);
    asm volatile("ldmatrix.sync.aligned.m8n8.x4.trans.shared.b16 {%0,%1,%2,%3}, [%4];"
        : "=r"(r[0]), "=r"(r[1]), "=r"(r[2]), "=r"(r[3]) : "r"(a));
}
__device__ __forceinline__ void mma_f16(float* d, const uint32_t* a, const uint32_t* b) {
    asm volatile(
        "mma.sync.aligned.m16n8k16.row.col.f32.f16.f16.f32 "
        "{%0,%1,%2,%3}, {%4,%5,%6,%7}, {%8,%9}, {%0,%1,%2,%3};"
        : "+f"(d[0]), "+f"(d[1]), "+f"(d[2]), "+f"(d[3])
        : "r"(a[0]), "r"(a[1]), "r"(a[2]), "r"(a[3]), "r"(b[0]), "r"(b[1]));
}
__device__ __forceinline__ __half2 h2(float x, float y) { return __floats2half2_rn(x, y); }

// ---------------------------------------------------------------------------
// fp16 projection GEMM: P[b,h,s,k] = sum_d X[b,s,d] * W[h,d,k]
// Block 128(M)x64(N), BK=32, 256 thr = 8 warps (4m x 2n), warp tile 32x32.
// Register-prefetch pipelined staging. which: 0->q (x1/8), 1->k, 2->v
// ---------------------------------------------------------------------------
__global__ __launch_bounds__(256) void proj_f16(const float* __restrict__ X,
                                                const float* __restrict__ W,
                                                int which) {
    const int tile = blockIdx.x, h = blockIdx.y, b = blockIdx.z;
    const int tid = threadIdx.x;
    const int warp = tid >> 5, lane = tid & 31;
    const int wm = warp & 3, wn = warp >> 2;
    const int lq = lane >> 2, lp = lane & 3;

    __shared__ __half As[128][40];
    __shared__ __half Bs[32][72];

    const float* Xb = X + (size_t)(b * SS + tile * 128) * DD;
    const float* Wh = W + (size_t)h * DD * DKK;

    float acc[2][4][4];
#pragma unroll
    for (int mi = 0; mi < 2; mi++)
#pragma unroll
        for (int ni = 0; ni < 4; ni++)
#pragma unroll
            for (int c = 0; c < 4; c++) acc[mi][ni][c] = 0.f;

    const int ar = tid >> 1, ac = (tid & 1) * 16;   // A: 16 floats/thread
    const int br = tid >> 3, bc = (tid & 7) * 8;    // B: 8 floats/thread

    const float* aptr = Xb + (size_t)ar * DD + ac;
    const float* bptr = Wh + (size_t)br * DKK + bc;

    float4 fa[4], fb[2];
#pragma unroll
    for (int i = 0; i < 4; i++) fa[i] = *(const float4*)(aptr + i * 4);
    fb[0] = *(const float4*)(bptr);
    fb[1] = *(const float4*)(bptr + 4);

    for (int k0 = 0; k0 < DD; k0 += 32) {
        union { uint4 u; __half2 hh[4]; } p0, p1, pb;
        p0.hh[0] = h2(fa[0].x, fa[0].y); p0.hh[1] = h2(fa[0].z, fa[0].w);
        p0.hh[2] = h2(fa[1].x, fa[1].y); p0.hh[3] = h2(fa[1].z, fa[1].w);
        p1.hh[0] = h2(fa[2].x, fa[2].y); p1.hh[1] = h2(fa[2].z, fa[2].w);
        p1.hh[2] = h2(fa[3].x, fa[3].y); p1.hh[3] = h2(fa[3].z, fa[3].w);
        pb.hh[0] = h2(fb[0].x, fb[0].y); pb.hh[1] = h2(fb[0].z, fb[0].w);
        pb.hh[2] = h2(fb[1].x, fb[1].y); pb.hh[3] = h2(fb[1].z, fb[1].w);
        *(uint4*)&As[ar][ac]     = p0.u;
        *(uint4*)&As[ar][ac + 8] = p1.u;
        *(uint4*)&Bs[br][bc]     = pb.u;
        __syncthreads();

        if (k0 + 32 < DD) {
            const float* an = aptr + k0 + 32;
            const float* bn = bptr + (size_t)(k0 + 32) * DKK;
#pragma unroll
            for (int i = 0; i < 4; i++) fa[i] = *(const float4*)(an + i * 4);
            fb[0] = *(const float4*)(bn);
            fb[1] = *(const float4*)(bn + 4);
        }

#pragma unroll
        for (int kk = 0; kk < 2; kk++) {
            uint32_t af[2][4], bf[2][4];
#pragma unroll
            for (int mi = 0; mi < 2; mi++)
                ldsm4(af[mi], &As[wm * 32 + mi * 16 + (lane & 15)][kk * 16 + (lane >> 4) * 8]);
#pragma unroll
            for (int np = 0; np < 2; np++)
                ldsm4t(bf[np], &Bs[kk * 16 + (lane & 15)][wn * 32 + np * 16 + (lane >> 4) * 8]);
#pragma unroll
            for (int mi = 0; mi < 2; mi++)
#pragma unroll
                for (int np = 0; np < 2; np++) {
                    mma_f16(acc[mi][2 * np],     af[mi], &bf[np][0]);
                    mma_f16(acc[mi][2 * np + 1], af[mi], &bf[np][2]);
                }
        }
        __syncthreads();
    }

    const float osc = (which == 0) ? 0.125f : 1.0f;
    __half* P = (which == 0) ? g_qp : (which == 1) ? g_kp : g_vp;
    const size_t base = (size_t)(b * HH + h) * SS * DKK;
    const int srow = tile * 128 + wm * 32;
#pragma unroll
    for (int mi = 0; mi < 2; mi++)
#pragma unroll
        for (int ni = 0; ni < 4; ni++) {
            const int r0 = srow + mi * 16 + lq;
            const int col = wn * 32 + ni * 8 + 2 * lp;
            *(__half2*)(P + base + (size_t)r0 * DKK + col) =
                h2(acc[mi][ni][0] * osc, acc[mi][ni][1] * osc);
            *(__half2*)(P + base + (size_t)(r0 + 8) * DKK + col) =
                h2(acc[mi][ni][2] * osc, acc[mi][ni][3] * osc);
        }
}

// ---------------------------------------------------------------------------
// Flash attention, all-fp16 mma (m16n8k16). Block: 64 q-rows, 4 warps.
// K frags: ldmatrix non-trans. V frags: ldmatrix trans (no transpose staging).
// ---------------------------------------------------------------------------
__global__ __launch_bounds__(128) void attn_kernel() {
    const int qtile = blockIdx.x;      // S/64
    const int h = blockIdx.y, b = blockIdx.z;
    const int tid = threadIdx.x;
    const int wid = tid >> 5;
    const int lane = tid & 31;
    const int lq = lane >> 2;
    const int lp = lane & 3;

    const __half* qp = g_qp + (size_t)(b * HH + h) * SS * DKK;
    const __half* kp = g_kp + (size_t)(b * HH + h) * SS * DKK;
    const __half* vp = g_vp + (size_t)(b * HH + h) * SS * DKK;

    __shared__ __half Ks[64][72];
    __shared__ __half Vs[64][72];

    // Q fragments: m16 x k64 = 4 k16 steps (Q already scaled by 1/8)
    const int qrow0 = qtile * 64 + wid * 16;
    uint32_t aq[4][4];
#pragma unroll
    for (int kk = 0; kk < 4; kk++) {
        const int d0 = kk * 16 + 2 * lp;
        aq[kk][0] = *(const uint32_t*)(qp + (size_t)(qrow0 + lq)     * DKK + d0);
        aq[kk][1] = *(const uint32_t*)(qp + (size_t)(qrow0 + lq + 8) * DKK + d0);
        aq[kk][2] = *(const uint32_t*)(qp + (size_t)(qrow0 + lq)     * DKK + d0 + 8);
        aq[kk][3] = *(const uint32_t*)(qp + (size_t)(qrow0 + lq + 8) * DKK + d0 + 8);
    }

    float oacc[8][4];
#pragma unroll
    for (int j = 0; j < 8; j++)
#pragma unroll
        for (int c = 0; c < 4; c++) oacc[j][c] = 0.f;

    float m0 = -INFINITY, m1 = -INFINITY;
    float l0 = 0.f, l1 = 0.f;

    const int ntiles = qtile + 1;
    const int qi0 = qrow0 + lq;
    const int qi1 = qi0 + 8;

    const int srow = tid >> 1;
    const int scb = (tid & 1) * 32;

    for (int kt = 0; kt < ntiles; kt++) {
        // stage K and V tiles (row-major, 64x64 halves each)
        {
            const __half* ksrc = kp + (size_t)(kt * 64 + srow) * DKK + scb;
            const __half* vsrc = vp + (size_t)(kt * 64 + srow) * DKK + scb;
#pragma unroll
            for (int i = 0; i < 4; i++) {
                *(uint4*)&Ks[srow][scb + i * 8] = *(const uint4*)(ksrc + i * 8);
                *(uint4*)&Vs[srow][scb + i * 8] = *(const uint4*)(vsrc + i * 8);
            }
        }
        __syncthreads();

        // ---- S = Q @ K^T ----
        float sacc[8][4];
#pragma unroll
        for (int j = 0; j < 8; j++)
#pragma unroll
            for (int c = 0; c < 4; c++) sacc[j][c] = 0.f;

#pragma unroll
        for (int kk = 0; kk < 4; kk++) {
#pragma unroll
            for (int jp = 0; jp < 4; jp++) {
                uint32_t bk[4];
                const int kr = jp * 16 + ((lane >> 4) & 1) * 8 + (lane & 7);
                const int kc = kk * 16 + ((lane >> 3) & 1) * 8;
                ldsm4(bk, &Ks[kr][kc]);
                mma_f16(sacc[2 * jp],     aq[kk], &bk[0]);
                mma_f16(sacc[2 * jp + 1], aq[kk], &bk[2]);
            }
        }

        // ---- causal mask (diagonal tile only) ----
        if (kt == qtile) {
#pragma unroll
            for (int j = 0; j < 8; j++) {
                const int kj = kt * 64 + j * 8 + lp * 2;
                if (kj     > qi0) sacc[j][0] = -INFINITY;
                if (kj + 1 > qi0) sacc[j][1] = -INFINITY;
                if (kj     > qi1) sacc[j][2] = -INFINITY;
                if (kj + 1 > qi1) sacc[j][3] = -INFINITY;
            }
        }

        // ---- online softmax ----
        float t0 = -INFINITY, t1 = -INFINITY;
#pragma unroll
        for (int j = 0; j < 8; j++) {
            t0 = fmaxf(t0, fmaxf(sacc[j][0], sacc[j][1]));
            t1 = fmaxf(t1, fmaxf(sacc[j][2], sacc[j][3]));
        }
        t0 = fmaxf(t0, __shfl_xor_sync(0xffffffff, t0, 1));
        t0 = fmaxf(t0, __shfl_xor_sync(0xffffffff, t0, 2));
        t1 = fmaxf(t1, __shfl_xor_sync(0xffffffff, t1, 1));
        t1 = fmaxf(t1, __shfl_xor_sync(0xffffffff, t1, 2));

        const float mn0 = fmaxf(m0, t0), mn1 = fmaxf(m1, t1);
        const float corr0 = __expf(m0 - mn0), corr1 = __expf(m1 - mn1);
        m0 = mn0; m1 = mn1;

        float ls0 = 0.f, ls1 = 0.f;
#pragma unroll
        for (int j = 0; j < 8; j++) {
            sacc[j][0] = __expf(sacc[j][0] - mn0);
            sacc[j][1] = __expf(sacc[j][1] - mn0);
            sacc[j][2] = __expf(sacc[j][2] - mn1);
            sacc[j][3] = __expf(sacc[j][3] - mn1);
            ls0 += sacc[j][0] + sacc[j][1];
            ls1 += sacc[j][2] + sacc[j][3];
        }
        l0 = l0 * corr0 + ls0;
        l1 = l1 * corr1 + ls1;
#pragma unroll
        for (int j = 0; j < 8; j++) {
            oacc[j][0] *= corr0; oacc[j][1] *= corr0;
            oacc[j][2] *= corr1; oacc[j][3] *= corr1;
        }

        // ---- P (fp16 register identity) @ V ----
#pragma unroll
        for (int ks = 0; ks < 4; ks++) {
            uint32_t ap[4];
            union { uint32_t u; __half2 hh; } c0, c1, c2, c3;
            c0.hh = h2(sacc[2*ks][0],   sacc[2*ks][1]);
            c1.hh = h2(sacc[2*ks][2],   sacc[2*ks][3]);
            c2.hh = h2(sacc[2*ks+1][0], sacc[2*ks+1][1]);
            c3.hh = h2(sacc[2*ks+1][2], sacc[2*ks+1][3]);
            ap[0] = c0.u; ap[1] = c1.u; ap[2] = c2.u; ap[3] = c3.u;
#pragma unroll
            for (int np = 0; np < 4; np++) {
                uint32_t bv[4];
                const int vr = ks * 16 + (lane & 15);
                const int vc = np * 16 + (lane >> 4) * 8;
                ldsm4t(bv, &Vs[vr][vc]);
                mma_f16(oacc[2 * np],     ap, &bv[0]);
                mma_f16(oacc[2 * np + 1], ap, &bv[2]);
            }
        }
        __syncthreads();
    }

    l0 += __shfl_xor_sync(0xffffffff, l0, 1);
    l0 += __shfl_xor_sync(0xffffffff, l0, 2);
    l1 += __shfl_xor_sync(0xffffffff, l1, 1);
    l1 += __shfl_xor_sync(0xffffffff, l1, 2);
    const float inv0 = 1.f / l0, inv1 = 1.f / l1;

    __half* ao = g_ao + (size_t)b * SS * DD + (size_t)h * DKK;
#pragma unroll
    for (int j = 0; j < 8; j++) {
        const int dk = j * 8 + lp * 2;
        *(__half2*)(ao + (size_t)qi0 * DD + dk) = h2(oacc[j][0] * inv0, oacc[j][1] * inv0);
        *(__half2*)(ao + (size_t)qi1 * DD + dk) = h2(oacc[j][2] * inv1, oacc[j][3] * inv1);
    }
}

// ---------------------------------------------------------------------------
// fp16 output projection: Y[m,n] = sum_k AO[m,k] * Wo[n,k] + bo[n]
// A already fp16 (g_ao). B = Wo rows are k-contiguous -> non-trans ldsm.
// ---------------------------------------------------------------------------
__global__ __launch_bounds__(256) void outproj_f16(const float* __restrict__ Wo,
                                                   const float* __restrict__ bo,
                                                   float* __restrict__ Y) {
    const int mt = blockIdx.x, nt = blockIdx.y;
    const int tid = threadIdx.x;
    const int warp = tid >> 5, lane = tid & 31;
    const int wm = warp & 3, wn = warp >> 2;
    const int lq = lane >> 2, lp = lane & 3;

    __shared__ __half As[128][40];
    __shared__ __half Bs[64][40];

    const __half* Xb = g_ao + (size_t)mt * 128 * DD;

    float acc[2][4][4];
#pragma unroll
    for (int mi = 0; mi < 2; mi++)
#pragma unroll
        for (int ni = 0; ni < 4; ni++)
#pragma unroll
            for (int c = 0; c < 4; c++) acc[mi][ni][c] = 0.f;

    const int ar = tid >> 1, ac = (tid & 1) * 16;   // A: 16 halves/thread
    const int bn = tid >> 2, bkc = (tid & 3) * 8;   // B: 8 floats/thread

    const __half* aptr = Xb + (size_t)ar * DD + ac;
    const float*  bptr = Wo + (size_t)(nt * 64 + bn) * DD + bkc;

    uint4 ua[2];
    float4 fb[2];
    ua[0] = *(const uint4*)(aptr);
    ua[1] = *(const uint4*)(aptr + 8);
    fb[0] = *(const float4*)(bptr);
    fb[1] = *(const float4*)(bptr + 4);

    for (int k0 = 0; k0 < DD; k0 += 32) {
        union { uint4 u; __half2 hh[4]; } pb;
        pb.hh[0] = h2(fb[0].x, fb[0].y); pb.hh[1] = h2(fb[0].z, fb[0].w);
        pb.hh[2] = h2(fb[1].x, fb[1].y); pb.hh[3] = h2(fb[1].z, fb[1].w);
        *(uint4*)&As[ar][ac]     = ua[0];
        *(uint4*)&As[ar][ac + 8] = ua[1];
        *(uint4*)&Bs[bn][bkc]    = pb.u;
        __syncthreads();

        if (k0 + 32 < DD) {
            const __half* an = aptr + k0 + 32;
            const float*  bnp = bptr + k0 + 32;
            ua[0] = *(const uint4*)(an);
            ua[1] = *(const uint4*)(an + 8);
            fb[0] = *(const float4*)(bnp);
            fb[1] = *(const float4*)(bnp + 4);
        }

#pragma unroll
        for (int kk = 0; kk < 2; kk++) {
            uint32_t af[2][4], bf[2][4];
#pragma unroll
            for (int mi = 0; mi < 2; mi++)
                ldsm4(af[mi], &As[wm * 32 + mi * 16 + (lane & 15)][kk * 16 + (lane >> 4) * 8]);
#pragma unroll
            for (int np = 0; np < 2; np++) {
                const int nr = wn * 32 + np * 16 + ((lane >> 4) & 1) * 8 + (lane & 7);
                const int nc = kk * 16 + ((lane >> 3) & 1) * 8;
                ldsm4(bf[np], &Bs[nr][nc]);
            }
#pragma unroll
            for (int mi = 0; mi < 2; mi++)
#pragma unroll
                for (int np = 0; np < 2; np++) {
                    mma_f16(acc[mi][2 * np],     af[mi], &bf[np][0]);
                    mma_f16(acc[mi][2 * np + 1], af[mi], &bf[np][2]);
                }
        }
        __syncthreads();
    }

#pragma unroll
    for (int mi = 0; mi < 2; mi++)
#pragma unroll
        for (int ni = 0; ni < 4; ni++) {
            const int r0 = mt * 128 + wm * 32 + mi * 16 + lq;
            const int col = nt * 64 + wn * 32 + ni * 8 + 2 * lp;
            const float b0 = bo[col], b1 = bo[col + 1];
            *(float2*)(Y + (size_t)r0 * DD + col) =
                make_float2(acc[mi][ni][0] + b0, acc[mi][ni][1] + b1);
            *(float2*)(Y + (size_t)(r0 + 8) * DD + col) =
                make_float2(acc[mi][ni][2] + b0, acc[mi][ni][3] + b1);
        }
}

// ---------------------------------------------------------------------------
extern "C" void kernel_launch(void* const* d_in, const int* in_sizes, int n_in,
                              void* d_out, int out_size) {
    const float* query = (const float*)d_in[0];
    const float* key   = (const float*)d_in[1];
    const float* value = (const float*)d_in[2];
    const float* Wq    = (const float*)d_in[3];
    const float* Wk    = (const float*)d_in[4];
    const float* Wv    = (const float*)d_in[5];
    const float* Wo    = (const float*)d_in[6];
    const float* bo    = (const float*)d_in[7];
    float* out = (float*)d_out;

    dim3 pg(SS / 128, HH, BB);
    proj_f16<<<pg, 256>>>(query, Wq, 0);
    proj_f16<<<pg, 256>>>(key,   Wk, 1);
    proj_f16<<<pg, 256>>>(value, Wv, 2);

    attn_kernel<<<dim3(SS / 64, HH, BB), 128>>>();

    outproj_f16<<<dim3(BB * SS / 128, DD / 64), 256>>>(Wo, bo, out);
}

// round 7
// speedup vs baseline: 5.9102x; 1.2461x over previous
#include <cuda_runtime.h>
#include <cuda_fp16.h>
#include <math.h>
#include <stdint.h>

#define BB  2
#define SS  2048
#define DD  1024
#define HH  16
#define DKK 64

// Scratch, all fp16. Layout [b, s, h*64+k] (row-major [4096, 1024]).
__device__ __half g_qp[BB*SS*DD];   // q pre-scaled by 1/8
__device__ __half g_kp[BB*SS*DD];
__device__ __half g_vp[BB*SS*DD];
__device__ __half g_ao[BB*SS*DD];

// ---------------------------------------------------------------------------
// helpers
// ---------------------------------------------------------------------------
__device__ __forceinline__ void ldsm4(uint32_t* r, const void* p) {
    uint32_t a = (uint32_t)__cvta_generic_to_shared(p);
    asm volatile("ldmatrix.sync.aligned.m8n8.x4.shared.b16 {%0,%1,%2,%3}, [%4];"
        : "=r"(r[0]), "=r"(r[1]), "=r"(r[2]), "=r"(r[3]) : "r"(a));
}
__device__ __forceinline__ void ldsm4t(uint32_t* r, const void* p) {
    uint32_t a = (uint32_t)__cvta_generic_to_shared(p);
    asm volatile("ldmatrix.sync.aligned.m8n8.x4.trans.shared.b16 {%0,%1,%2,%3}, [%4];"
        : "=r"(r[0]), "=r"(r[1]), "=r"(r[2]), "=r"(r[3]) : "r"(a));
}
__device__ __forceinline__ void mma_f16(float* d, const uint32_t* a, const uint32_t* b) {
    asm volatile(
        "mma.sync.aligned.m16n8k16.row.col.f32.f16.f16.f32 "
        "{%0,%1,%2,%3}, {%4,%5,%6,%7}, {%8,%9}, {%0,%1,%2,%3};"
        : "+f"(d[0]), "+f"(d[1]), "+f"(d[2]), "+f"(d[3])
        : "r"(a[0]), "r"(a[1]), "r"(a[2]), "r"(a[3]), "r"(b[0]), "r"(b[1]));
}
__device__ __forceinline__ __half2 h2(float x, float y) { return __floats2half2_rn(x, y); }
__device__ __forceinline__ uint4 cvt8(float4 a, float4 b) {
    union { uint4 u; __half2 hh[4]; } r;
    r.hh[0] = h2(a.x, a.y); r.hh[1] = h2(a.z, a.w);
    r.hh[2] = h2(b.x, b.y); r.hh[3] = h2(b.z, b.w);
    return r.u;
}

// ---------------------------------------------------------------------------
// Merged-head projection GEMM: C[4096,1024] = X[4096,1024] @ Wcat[1024,1024]
// Wcat[d, h*64+k] = W[h,d,k] (gather in staging). Block 128x128, BK=32,
// 8 warps (2m x 4n), warp tile 64x32. Double-buffered smem, fp32->fp16 cvt.
// blockIdx.z selects q/k/v. q is pre-scaled by 1/8.
// ---------------------------------------------------------------------------
__global__ __launch_bounds__(256) void proj_f16(
    const float* __restrict__ Xq, const float* __restrict__ Xk,
    const float* __restrict__ Xv, const float* __restrict__ Wq,
    const float* __restrict__ Wk, const float* __restrict__ Wv) {
    const int mt = blockIdx.x, nt = blockIdx.y, which = blockIdx.z;
    const float* X = (which == 0) ? Xq : (which == 1) ? Xk : Xv;
    const float* W = (which == 0) ? Wq : (which == 1) ? Wk : Wv;
    __half* P = (which == 0) ? g_qp : (which == 1) ? g_kp : g_vp;
    const float osc = (which == 0) ? 0.125f : 1.0f;

    const int tid = threadIdx.x, warp = tid >> 5, lane = tid & 31;
    const int wm = warp & 1, wn = warp >> 1;
    const int lq = lane >> 2, lp = lane & 3;

    __shared__ __half As[2][128][40];
    __shared__ __half Bs[2][32][136];

    float acc[4][4][4];
#pragma unroll
    for (int mi = 0; mi < 4; mi++)
#pragma unroll
        for (int ni = 0; ni < 4; ni++)
#pragma unroll
            for (int c = 0; c < 4; c++) acc[mi][ni][c] = 0.f;

    const int ar = tid >> 1, ac = (tid & 1) * 16;
    const int br = tid >> 3, bc = (tid & 7) * 16;
    const int gn0 = nt * 128 + bc;
    const int hW = gn0 >> 6, kc0 = gn0 & 63;

    const float* aptr = X + (size_t)(mt * 128 + ar) * DD + ac;
    const float* bptr = W + (size_t)hW * DD * DKK + kc0;

    float4 fa[4], fb[4];
#pragma unroll
    for (int i = 0; i < 4; i++) {
        fa[i] = *(const float4*)(aptr + i * 4);
        fb[i] = *(const float4*)(bptr + (size_t)br * DKK + i * 4);
    }
    *(uint4*)&As[0][ar][ac]     = cvt8(fa[0], fa[1]);
    *(uint4*)&As[0][ar][ac + 8] = cvt8(fa[2], fa[3]);
    *(uint4*)&Bs[0][br][bc]     = cvt8(fb[0], fb[1]);
    *(uint4*)&Bs[0][br][bc + 8] = cvt8(fb[2], fb[3]);
    __syncthreads();

    for (int k0 = 0; k0 < DD; k0 += 32) {
        const int s = (k0 >> 5) & 1;
        const bool more = (k0 + 32) < DD;
        if (more) {
            const float* an = aptr + k0 + 32;
            const float* bn = bptr + (size_t)(k0 + 32 + br) * DKK;
#pragma unroll
            for (int i = 0; i < 4; i++) {
                fa[i] = *(const float4*)(an + i * 4);
                fb[i] = *(const float4*)(bn + i * 4);
            }
        }
#pragma unroll
        for (int kk = 0; kk < 2; kk++) {
            uint32_t af[4][4], bf[2][4];
#pragma unroll
            for (int mi = 0; mi < 4; mi++)
                ldsm4(af[mi], &As[s][wm * 64 + mi * 16 + (lane & 15)][kk * 16 + (lane >> 4) * 8]);
#pragma unroll
            for (int np = 0; np < 2; np++)
                ldsm4t(bf[np], &Bs[s][kk * 16 + (lane & 15)][wn * 32 + np * 16 + (lane >> 4) * 8]);
#pragma unroll
            for (int mi = 0; mi < 4; mi++)
#pragma unroll
                for (int np = 0; np < 2; np++) {
                    mma_f16(acc[mi][2 * np],     af[mi], &bf[np][0]);
                    mma_f16(acc[mi][2 * np + 1], af[mi], &bf[np][2]);
                }
        }
        if (more) {
            *(uint4*)&As[s ^ 1][ar][ac]     = cvt8(fa[0], fa[1]);
            *(uint4*)&As[s ^ 1][ar][ac + 8] = cvt8(fa[2], fa[3]);
            *(uint4*)&Bs[s ^ 1][br][bc]     = cvt8(fb[0], fb[1]);
            *(uint4*)&Bs[s ^ 1][br][bc + 8] = cvt8(fb[2], fb[3]);
        }
        __syncthreads();
    }

#pragma unroll
    for (int mi = 0; mi < 4; mi++)
#pragma unroll
        for (int ni = 0; ni < 4; ni++) {
            const int row = mt * 128 + wm * 64 + mi * 16 + lq;
            const int col = nt * 128 + wn * 32 + ni * 8 + 2 * lp;
            *(__half2*)(P + (size_t)row * DD + col) =
                h2(acc[mi][ni][0] * osc, acc[mi][ni][1] * osc);
            *(__half2*)(P + (size_t)(row + 8) * DD + col) =
                h2(acc[mi][ni][2] * osc, acc[mi][ni][3] * osc);
        }
}

// ---------------------------------------------------------------------------
// Flash attention. Block = 128 q-rows, 4 warps (m32 each), KV tile 64.
// Q/K/V in [b,s,h,k] layout (row stride DD).
// ---------------------------------------------------------------------------
__global__ __launch_bounds__(128) void attn_kernel() {
    const int qtile = blockIdx.x;      // S/128
    const int h = blockIdx.y, b = blockIdx.z;
    const int tid = threadIdx.x;
    const int wid = tid >> 5;
    const int lane = tid & 31;
    const int lq = lane >> 2;
    const int lp = lane & 3;

    const size_t base = (size_t)b * SS * DD + h * DKK;
    const __half* qp = g_qp + base;
    const __half* kp = g_kp + base;
    const __half* vp = g_vp + base;

    __shared__ __half Ks[64][72];
    __shared__ __half Vs[64][72];

    const int qrow0 = qtile * 128 + wid * 32;
    uint32_t aq[2][4][4];
#pragma unroll
    for (int mi = 0; mi < 2; mi++)
#pragma unroll
        for (int kk = 0; kk < 4; kk++) {
            const int d0 = kk * 16 + 2 * lp;
            const int r0 = qrow0 + mi * 16 + lq;
            aq[mi][kk][0] = *(const uint32_t*)(qp + (size_t)r0 * DD + d0);
            aq[mi][kk][1] = *(const uint32_t*)(qp + (size_t)(r0 + 8) * DD + d0);
            aq[mi][kk][2] = *(const uint32_t*)(qp + (size_t)r0 * DD + d0 + 8);
            aq[mi][kk][3] = *(const uint32_t*)(qp + (size_t)(r0 + 8) * DD + d0 + 8);
        }

    float oacc[2][8][4];
#pragma unroll
    for (int mi = 0; mi < 2; mi++)
#pragma unroll
        for (int j = 0; j < 8; j++)
#pragma unroll
            for (int c = 0; c < 4; c++) oacc[mi][j][c] = 0.f;

    float mx[2][2] = {{-INFINITY, -INFINITY}, {-INFINITY, -INFINITY}};
    float ll[2][2] = {{0.f, 0.f}, {0.f, 0.f}};

    const int ntiles = 2 * qtile + 2;
    const int srow = tid >> 1;
    const int scb = (tid & 1) * 32;

    for (int kt = 0; kt < ntiles; kt++) {
        {
            const __half* ksrc = kp + (size_t)(kt * 64 + srow) * DD + scb;
            const __half* vsrc = vp + (size_t)(kt * 64 + srow) * DD + scb;
#pragma unroll
            for (int i = 0; i < 4; i++) {
                *(uint4*)&Ks[srow][scb + i * 8] = *(const uint4*)(ksrc + i * 8);
                *(uint4*)&Vs[srow][scb + i * 8] = *(const uint4*)(vsrc + i * 8);
            }
        }
        __syncthreads();

        if (kt * 64 <= qrow0 + 31) {   // tile not fully masked for this warp
            float sacc[2][8][4];
#pragma unroll
            for (int mi = 0; mi < 2; mi++)
#pragma unroll
                for (int j = 0; j < 8; j++)
#pragma unroll
                    for (int c = 0; c < 4; c++) sacc[mi][j][c] = 0.f;

#pragma unroll
            for (int kk = 0; kk < 4; kk++) {
#pragma unroll
                for (int jp = 0; jp < 4; jp++) {
                    uint32_t bk[4];
                    const int kr = jp * 16 + ((lane >> 4) & 1) * 8 + (lane & 7);
                    const int kc = kk * 16 + ((lane >> 3) & 1) * 8;
                    ldsm4(bk, &Ks[kr][kc]);
#pragma unroll
                    for (int mi = 0; mi < 2; mi++) {
                        mma_f16(sacc[mi][2 * jp],     aq[mi][kk], &bk[0]);
                        mma_f16(sacc[mi][2 * jp + 1], aq[mi][kk], &bk[2]);
                    }
                }
            }

            if (kt * 64 + 63 > qrow0) {   // tile intersects diagonal
#pragma unroll
                for (int mi = 0; mi < 2; mi++) {
                    const int qi0 = qrow0 + mi * 16 + lq;
                    const int qi1 = qi0 + 8;
#pragma unroll
                    for (int j = 0; j < 8; j++) {
                        const int kj = kt * 64 + j * 8 + lp * 2;
                        if (kj     > qi0) sacc[mi][j][0] = -INFINITY;
                        if (kj + 1 > qi0) sacc[mi][j][1] = -INFINITY;
                        if (kj     > qi1) sacc[mi][j][2] = -INFINITY;
                        if (kj + 1 > qi1) sacc[mi][j][3] = -INFINITY;
                    }
                }
            }

            // online softmax per row group (mi, half)
#pragma unroll
            for (int mi = 0; mi < 2; mi++) {
                float t0 = -INFINITY, t1 = -INFINITY;
#pragma unroll
                for (int j = 0; j < 8; j++) {
                    t0 = fmaxf(t0, fmaxf(sacc[mi][j][0], sacc[mi][j][1]));
                    t1 = fmaxf(t1, fmaxf(sacc[mi][j][2], sacc[mi][j][3]));
                }
                t0 = fmaxf(t0, __shfl_xor_sync(0xffffffff, t0, 1));
                t0 = fmaxf(t0, __shfl_xor_sync(0xffffffff, t0, 2));
                t1 = fmaxf(t1, __shfl_xor_sync(0xffffffff, t1, 1));
                t1 = fmaxf(t1, __shfl_xor_sync(0xffffffff, t1, 2));
                const float mn0 = fmaxf(mx[mi][0], t0);
                const float mn1 = fmaxf(mx[mi][1], t1);
                const float corr0 = __expf(mx[mi][0] - mn0);
                const float corr1 = __expf(mx[mi][1] - mn1);
                mx[mi][0] = mn0; mx[mi][1] = mn1;

                float ls0 = 0.f, ls1 = 0.f;
#pragma unroll
                for (int j = 0; j < 8; j++) {
                    sacc[mi][j][0] = __expf(sacc[mi][j][0] - mn0);
                    sacc[mi][j][1] = __expf(sacc[mi][j][1] - mn0);
                    sacc[mi][j][2] = __expf(sacc[mi][j][2] - mn1);
                    sacc[mi][j][3] = __expf(sacc[mi][j][3] - mn1);
                    ls0 += sacc[mi][j][0] + sacc[mi][j][1];
                    ls1 += sacc[mi][j][2] + sacc[mi][j][3];
                }
                ll[mi][0] = ll[mi][0] * corr0 + ls0;
                ll[mi][1] = ll[mi][1] * corr1 + ls1;
#pragma unroll
                for (int j = 0; j < 8; j++) {
                    oacc[mi][j][0] *= corr0; oacc[mi][j][1] *= corr0;
                    oacc[mi][j][2] *= corr1; oacc[mi][j][3] *= corr1;
                }
            }

            // P @ V  (P fp16 register identity)
#pragma unroll
            for (int ks = 0; ks < 4; ks++) {
                uint32_t ap[2][4];
#pragma unroll
                for (int mi = 0; mi < 2; mi++) {
                    union { uint32_t u; __half2 hh; } c0, c1, c2, c3;
                    c0.hh = h2(sacc[mi][2*ks][0],   sacc[mi][2*ks][1]);
                    c1.hh = h2(sacc[mi][2*ks][2],   sacc[mi][2*ks][3]);
                    c2.hh = h2(sacc[mi][2*ks+1][0], sacc[mi][2*ks+1][1]);
                    c3.hh = h2(sacc[mi][2*ks+1][2], sacc[mi][2*ks+1][3]);
                    ap[mi][0] = c0.u; ap[mi][1] = c1.u;
                    ap[mi][2] = c2.u; ap[mi][3] = c3.u;
                }
#pragma unroll
                for (int np = 0; np < 4; np++) {
                    uint32_t bv[4];
                    ldsm4t(bv, &Vs[ks * 16 + (lane & 15)][np * 16 + (lane >> 4) * 8]);
#pragma unroll
                    for (int mi = 0; mi < 2; mi++) {
                        mma_f16(oacc[mi][2 * np],     ap[mi], &bv[0]);
                        mma_f16(oacc[mi][2 * np + 1], ap[mi], &bv[2]);
                    }
                }
            }
        }
        __syncthreads();
    }

#pragma unroll
    for (int mi = 0; mi < 2; mi++)
#pragma unroll
        for (int r = 0; r < 2; r++) {
            ll[mi][r] += __shfl_xor_sync(0xffffffff, ll[mi][r], 1);
            ll[mi][r] += __shfl_xor_sync(0xffffffff, ll[mi][r], 2);
        }

    __half* ao = g_ao + base;
#pragma unroll
    for (int mi = 0; mi < 2; mi++) {
        const float inv0 = 1.f / ll[mi][0];
        const float inv1 = 1.f / ll[mi][1];
        const int r0 = qrow0 + mi * 16 + lq;
#pragma unroll
        for (int j = 0; j < 8; j++) {
            const int dk = j * 8 + lp * 2;
            *(__half2*)(ao + (size_t)r0 * DD + dk) =
                h2(oacc[mi][j][0] * inv0, oacc[mi][j][1] * inv0);
            *(__half2*)(ao + (size_t)(r0 + 8) * DD + dk) =
                h2(oacc[mi][j][2] * inv1, oacc[mi][j][3] * inv1);
        }
    }
}

// ---------------------------------------------------------------------------
// Output projection: Y[4096,1024] = AO @ Wo^T + bo. Block 128x128, BK=32,
// double-buffered. A fp16 direct; B (Wo rows, k-contig) cvt fp32->fp16.
// ---------------------------------------------------------------------------
__global__ __launch_bounds__(256) void outproj_f16(const float* __restrict__ Wo,
                                                   const float* __restrict__ bo,
                                                   float* __restrict__ Y) {
    const int mt = blockIdx.x, nt = blockIdx.y;
    const int tid = threadIdx.x, warp = tid >> 5, lane = tid & 31;
    const int wm = warp & 1, wn = warp >> 1;
    const int lq = lane >> 2, lp = lane & 3;

    __shared__ __half As[2][128][40];
    __shared__ __half Bs[2][128][40];

    float acc[4][4][4];
#pragma unroll
    for (int mi = 0; mi < 4; mi++)
#pragma unroll
        for (int ni = 0; ni < 4; ni++)
#pragma unroll
            for (int c = 0; c < 4; c++) acc[mi][ni][c] = 0.f;

    const int ar = tid >> 1, ac = (tid & 1) * 16;
    const int bn = tid >> 1, bkc = (tid & 1) * 16;

    const __half* aptr = g_ao + (size_t)(mt * 128 + ar) * DD + ac;
    const float*  bptr = Wo + (size_t)(nt * 128 + bn) * DD + bkc;

    uint4 ua[2];
    float4 fb[4];
    ua[0] = *(const uint4*)(aptr);
    ua[1] = *(const uint4*)(aptr + 8);
#pragma unroll
    for (int i = 0; i < 4; i++) fb[i] = *(const float4*)(bptr + i * 4);
    *(uint4*)&As[0][ar][ac]      = ua[0];
    *(uint4*)&As[0][ar][ac + 8]  = ua[1];
    *(uint4*)&Bs[0][bn][bkc]     = cvt8(fb[0], fb[1]);
    *(uint4*)&Bs[0][bn][bkc + 8] = cvt8(fb[2], fb[3]);
    __syncthreads();

    for (int k0 = 0; k0 < DD; k0 += 32) {
        const int s = (k0 >> 5) & 1;
        const bool more = (k0 + 32) < DD;
        if (more) {
            const __half* an = aptr + k0 + 32;
            const float* bn2 = bptr + k0 + 32;
            ua[0] = *(const uint4*)(an);
            ua[1] = *(const uint4*)(an + 8);
#pragma unroll
            for (int i = 0; i < 4; i++) fb[i] = *(const float4*)(bn2 + i * 4);
        }
#pragma unroll
        for (int kk = 0; kk < 2; kk++) {
            uint32_t af[4][4], bf[2][4];
#pragma unroll
            for (int mi = 0; mi < 4; mi++)
                ldsm4(af[mi], &As[s][wm * 64 + mi * 16 + (lane & 15)][kk * 16 + (lane >> 4) * 8]);
#pragma unroll
            for (int np = 0; np < 2; np++) {
                const int nr = wn * 32 + np * 16 + ((lane >> 4) & 1) * 8 + (lane & 7);
                const int nc = kk * 16 + ((lane >> 3) & 1) * 8;
                ldsm4(bf[np], &Bs[s][nr][nc]);
            }
#pragma unroll
            for (int mi = 0; mi < 4; mi++)
#pragma unroll
                for (int np = 0; np < 2; np++) {
                    mma_f16(acc[mi][2 * np],     af[mi], &bf[np][0]);
                    mma_f16(acc[mi][2 * np + 1], af[mi], &bf[np][2]);
                }
        }
        if (more) {
            *(uint4*)&As[s ^ 1][ar][ac]      = ua[0];
            *(uint4*)&As[s ^ 1][ar][ac + 8]  = ua[1];
            *(uint4*)&Bs[s ^ 1][bn][bkc]     = cvt8(fb[0], fb[1]);
            *(uint4*)&Bs[s ^ 1][bn][bkc + 8] = cvt8(fb[2], fb[3]);
        }
        __syncthreads();
    }

#pragma unroll
    for (int mi = 0; mi < 4; mi++)
#pragma unroll
        for (int ni = 0; ni < 4; ni++) {
            const int row = mt * 128 + wm * 64 + mi * 16 + lq;
            const int col = nt * 128 + wn * 32 + ni * 8 + 2 * lp;
            const float b0 = bo[col], b1 = bo[col + 1];
            *(float2*)(Y + (size_t)row * DD + col) =
                make_float2(acc[mi][ni][0] + b0, acc[mi][ni][1] + b1);
            *(float2*)(Y + (size_t)(row + 8) * DD + col) =
                make_float2(acc[mi][ni][2] + b0, acc[mi][ni][3] + b1);
        }
}

// ---------------------------------------------------------------------------
extern "C" void kernel_launch(void* const* d_in, const int* in_sizes, int n_in,
                              void* d_out, int out_size) {
    const float* query = (const float*)d_in[0];
    const float* key   = (const float*)d_in[1];
    const float* value = (const float*)d_in[2];
    const float* Wq    = (const float*)d_in[3];
    const float* Wk    = (const float*)d_in[4];
    const float* Wv    = (const float*)d_in[5];
    const float* Wo    = (const float*)d_in[6];
    const float* bo    = (const float*)d_in[7];
    float* out = (float*)d_out;

    proj_f16<<<dim3(BB * SS / 128, DD / 128, 3), 256>>>(query, key, value, Wq, Wk, Wv);

    attn_kernel<<<dim3(SS / 128, HH, BB), 128>>>();

    outproj_f16<<<dim3(BB * SS / 128, DD / 128), 256>>>(Wo, bo, out);
}